// round 1
// baseline (speedup 1.0000x reference)
#include <cuda_runtime.h>

#define NPTS 131072
#define BGR  64
#define NPG  2048
#define KNN  10
#define HD   64
#define CONV_BLOCKS (NPTS / 32)      // 4096
#define FULLMASK 0xffffffffu
#define PAIRNORM_EPS 1e-5f

// ---------------------------------------------------------------------------
// Device scratch (static — no allocations allowed)
// ---------------------------------------------------------------------------
__device__ int   d_order[NPTS];            // spatially sorted query order
__device__ int   d_knn[NPTS * KNN];        // global neighbor indices
__device__ float d_Zbuf[NPTS * HD];        // raw relu(conv) output z
__device__ float d_Ybuf[NPTS * HD];        // z @ Wx * invscale
__device__ float d_part[CONV_BLOCKS * 65]; // per-block stats partials (64 sums + sumsq)
__device__ float d_part2[64 * 65];         // stage-2 partials
__device__ float d_mean[HD];
__device__ float d_scaleInv;               // 1/sqrt(eps + mean row-norm^2)
__device__ float d_beff[HD];               // folded effective bias for next conv
__device__ int   d_pool[BGR * HD];         // pooled max (float bits, z>=0)

// ---------------------------------------------------------------------------
// init: zero the pool accumulator (must be re-zeroed every graph replay)
// ---------------------------------------------------------------------------
__global__ void init_kernel() {
    int i = blockIdx.x * blockDim.x + threadIdx.x;
    if (i < BGR * HD) d_pool[i] = 0;
}

// ---------------------------------------------------------------------------
// reorder: per-graph counting sort of query indices by Morton cell key.
// Only reassigns which thread processes which query (spatial locality for
// the kNN warp divergence); any within-cell order is equally correct.
// ---------------------------------------------------------------------------
__device__ __forceinline__ unsigned spreadbits(unsigned x) {
    x &= 0x0000ffffu;
    x = (x | (x << 8)) & 0x00FF00FFu;
    x = (x | (x << 4)) & 0x0F0F0F0Fu;
    x = (x | (x << 2)) & 0x33333333u;
    x = (x | (x << 1)) & 0x55555555u;
    return x;
}

__global__ __launch_bounds__(256) void reorder_kernel(const float2* __restrict__ pos) {
    __shared__ unsigned short skey[NPG];
    __shared__ int hist[1024];
    __shared__ int scanbuf[256];
    int g = blockIdx.x;
    int tid = threadIdx.x;
    int base = g * NPG;

    for (int c = tid; c < 1024; c += 256) hist[c] = 0;
    __syncthreads();

    for (int t = tid; t < NPG; t += 256) {
        float2 p = pos[base + t];
        int cx = (int)((p.x + 4.0f) * 4.0f);
        int cy = (int)((p.y + 4.0f) * 4.0f);
        cx = cx < 0 ? 0 : (cx > 31 ? 31 : cx);
        cy = cy < 0 ? 0 : (cy > 31 ? 31 : cy);
        unsigned key = spreadbits((unsigned)cx) | (spreadbits((unsigned)cy) << 1);
        skey[t] = (unsigned short)key;
        atomicAdd(&hist[key], 1);
    }
    __syncthreads();

    // scan 1024 cells: each thread owns 4
    int cb = tid * 4;
    int h0 = hist[cb], h1 = hist[cb + 1], h2 = hist[cb + 2], h3 = hist[cb + 3];
    int tot = h0 + h1 + h2 + h3;
    scanbuf[tid] = tot;
    __syncthreads();
    for (int off = 1; off < 256; off <<= 1) {
        int add = 0;
        if (tid >= off) add = scanbuf[tid - off];
        __syncthreads();
        scanbuf[tid] += add;
        __syncthreads();
    }
    int excl = scanbuf[tid] - tot;
    hist[cb]     = excl;
    hist[cb + 1] = excl + h0;
    hist[cb + 2] = excl + h0 + h1;
    hist[cb + 3] = excl + h0 + h1 + h2;
    __syncthreads();

    for (int t = tid; t < NPG; t += 256) {
        int key = skey[t];
        int rank = atomicAdd(&hist[key], 1);
        d_order[base + rank] = base + t;
    }
}

// ---------------------------------------------------------------------------
// kNN: brute-force per-thread top-10 with stable sorted insertion.
// d2 computed with __fmul_rn/__fadd_rn to match the reference bit-exactly.
// ---------------------------------------------------------------------------
#define INS(da, db, ia, ib) { if (db < da) { float _t = da; da = db; db = _t; int _u = ia; ia = ib; ib = _u; } }

__global__ __launch_bounds__(256) void knn_kernel(const float2* __restrict__ pos) {
    __shared__ float2 sp[NPG];
    int g = blockIdx.x >> 3;
    int chunk = blockIdx.x & 7;
    int base = g * NPG;

    for (int t = threadIdx.x; t < NPG; t += 256) sp[t] = pos[base + t];
    __syncthreads();

    int qslot = chunk * 256 + threadIdx.x;
    int qg = d_order[base + qslot];
    int qi = qg - base;
    float2 q = sp[qi];

    const float INF = __int_as_float(0x7f800000);
    float s0 = INF, s1 = INF, s2 = INF, s3 = INF, s4 = INF;
    float s5 = INF, s6 = INF, s7 = INF, s8 = INF, s9 = INF;
    int n0 = 0, n1 = 0, n2 = 0, n3 = 0, n4 = 0, n5 = 0, n6 = 0, n7 = 0, n8 = 0, n9 = 0;

#pragma unroll 4
    for (int j = 0; j < NPG; j++) {
        float2 c = sp[j];
        float dx = q.x - c.x;
        float dy = q.y - c.y;
        float d2 = __fadd_rn(__fmul_rn(dx, dx), __fmul_rn(dy, dy));
        if (d2 < s9 && j != qi) {
            s9 = d2; n9 = j;
            INS(s8, s9, n8, n9);
            INS(s7, s8, n7, n8);
            INS(s6, s7, n6, n7);
            INS(s5, s6, n5, n6);
            INS(s4, s5, n4, n5);
            INS(s3, s4, n3, n4);
            INS(s2, s3, n2, n3);
            INS(s1, s2, n1, n2);
            INS(s0, s1, n0, n1);
        }
    }
    int* op = d_knn + qg * KNN;
    op[0] = base + n0; op[1] = base + n1; op[2] = base + n2; op[3] = base + n3;
    op[4] = base + n4; op[5] = base + n5; op[6] = base + n6; op[7] = base + n7;
    op[8] = base + n8; op[9] = base + n9;
}

// ---------------------------------------------------------------------------
// deterministic block stats from s_z[32][HD] -> d_part[block][65]
// ---------------------------------------------------------------------------
__device__ __forceinline__ void block_stats(const float* s_z, float* s_red, int blockId) {
    int tid = threadIdx.x;
    if (tid < HD) {
        float s = 0.f, sq = 0.f;
#pragma unroll
        for (int r = 0; r < 32; r++) {
            float v = s_z[r * HD + tid];
            s += v;
            sq = fmaf(v, v, sq);
        }
        d_part[blockId * 65 + tid] = s;
        s_red[tid] = sq;
    }
    __syncthreads();
    if (tid < 32) {
        float v = s_red[tid] + s_red[tid + 32];
#pragma unroll
        for (int off = 16; off > 0; off >>= 1)
            v += __shfl_down_sync(FULLMASK, v, off);
        if (tid == 0) d_part[blockId * 65 + 64] = v;
    }
}

// ---------------------------------------------------------------------------
// conv1: msg = rel @ W1 + b1, max over 10 knn edges + self(rel=0 -> b1), relu
// one warp per 4 nodes, 2 features per lane
// ---------------------------------------------------------------------------
__global__ __launch_bounds__(256) void conv1_kernel(const float2* __restrict__ pos,
                                                    const float* __restrict__ W1,
                                                    const float* __restrict__ b1) {
    __shared__ float s_z[32 * HD];
    __shared__ float s_red[64];
    int tid = threadIdx.x, lane = tid & 31, wid = tid >> 5;
    int f0 = lane * 2, f1 = f0 + 1;
    float wx0 = W1[f0],      wx1 = W1[f1];
    float wy0 = W1[HD + f0], wy1 = W1[HD + f1];
    float bb0 = b1[f0],      bb1 = b1[f1];
    int nodebase = blockIdx.x * 32 + wid * 4;

    for (int it = 0; it < 4; it++) {
        int node = nodebase + it;
        float2 pi = pos[node];
        float m0 = bb0, m1 = bb1;                    // self edge: rel = 0
        float px = 0.f, py = 0.f;
        if (lane < KNN) {
            int jj = d_knn[node * KNN + lane];
            float2 pj = pos[jj];
            px = pj.x; py = pj.y;
        }
#pragma unroll
        for (int e = 0; e < KNN; e++) {
            float dx = __shfl_sync(FULLMASK, px, e) - pi.x;
            float dy = __shfl_sync(FULLMASK, py, e) - pi.y;
            m0 = fmaxf(m0, fmaf(dx, wx0, fmaf(dy, wy0, bb0)));
            m1 = fmaxf(m1, fmaf(dx, wx1, fmaf(dy, wy1, bb1)));
        }
        float z0 = fmaxf(m0, 0.f), z1 = fmaxf(m1, 0.f);
        *(float2*)&d_Zbuf[node * HD + f0] = make_float2(z0, z1);
        int r = wid * 4 + it;
        s_z[r * HD + f0] = z0;
        s_z[r * HD + f1] = z1;
    }
    __syncthreads();
    block_stats(s_z, s_red, blockIdx.x);
}

// ---------------------------------------------------------------------------
// stage-2 reduce: d_part[4096][65] -> d_part2[64][65]
// ---------------------------------------------------------------------------
__global__ __launch_bounds__(128) void reduce_kernel() {
    __shared__ float s_sq[16];
    int tid = threadIdx.x;
    int rbase = blockIdx.x * 64;
    if (tid < 64) {
        float s = 0.f;
        for (int r = 0; r < 64; r++) s += d_part[(rbase + r) * 65 + tid];
        d_part2[blockIdx.x * 65 + tid] = s;
    } else if (tid < 80) {
        int j = tid - 64;
        float s = 0.f;
        for (int r = 0; r < 4; r++) s += d_part[(rbase + j * 4 + r) * 65 + 64];
        s_sq[j] = s;
    }
    __syncthreads();
    if (tid == 64) {
        float s = 0.f;
        for (int j = 0; j < 16; j++) s += s_sq[j];
        d_part2[blockIdx.x * 65 + 64] = s;
    }
}

// ---------------------------------------------------------------------------
// final stats: mean, inv scale, and (if Wnext) folded effective bias
//   beff = bnext - inv * (mean @ Wnext_x)
// ---------------------------------------------------------------------------
__global__ __launch_bounds__(64) void stats_kernel(const float* __restrict__ Wnext,
                                                   const float* __restrict__ bnext) {
    __shared__ float smean[64];
    int tid = threadIdx.x;
    float s = 0.f;
    for (int r = 0; r < 64; r++) s += d_part2[r * 65 + tid];
    float mean = s * (1.0f / (float)NPTS);
    smean[tid] = mean;
    d_mean[tid] = mean;
    __syncthreads();
    if (tid == 0) {
        float sq = 0.f;
        for (int r = 0; r < 64; r++) sq += d_part2[r * 65 + 64];
        float ms = 0.f;
        for (int f = 0; f < 64; f++) ms = fmaf(smean[f], smean[f], ms);
        float denom = sq * (1.0f / (float)NPTS) - ms;
        d_scaleInv = 1.0f / sqrtf(PAIRNORM_EPS + denom);
    }
    __syncthreads();
    if (Wnext != nullptr) {
        float acc = 0.f;
        for (int k = 0; k < 64; k++) acc = fmaf(smean[k], Wnext[k * HD + tid], acc);
        d_beff[tid] = bnext[tid] - d_scaleInv * acc;
    }
}

// ---------------------------------------------------------------------------
// GEMM: d_Ybuf = d_Zbuf @ W[0:64,:] * d_scaleInv     (131072 x 64 x 64)
// thread-per-row, W staged in smem, k4-loop kept rolled (I-cache)
// ---------------------------------------------------------------------------
__global__ __launch_bounds__(128) void gemm_kernel(const float* __restrict__ W) {
    __shared__ float4 sw[1024];
    int tid = threadIdx.x;
    const float4* W4 = (const float4*)W;
    for (int i = tid; i < 1024; i += 128) sw[i] = W4[i];
    float inv = d_scaleInv;
    __syncthreads();

    int row = blockIdx.x * 128 + tid;
    const float4* zr = (const float4*)(d_Zbuf + row * HD);
    float acc[64];
#pragma unroll
    for (int c = 0; c < 64; c++) acc[c] = 0.f;

#pragma unroll 1
    for (int k4 = 0; k4 < 16; k4++) {
        float4 z4 = zr[k4];
#pragma unroll
        for (int kk = 0; kk < 4; kk++) {
            float zk = (kk == 0) ? z4.x : (kk == 1) ? z4.y : (kk == 2) ? z4.z : z4.w;
            int kI = k4 * 4 + kk;
#pragma unroll
            for (int c4 = 0; c4 < 16; c4++) {
                float4 w = sw[kI * 16 + c4];
                acc[c4 * 4 + 0] = fmaf(zk, w.x, acc[c4 * 4 + 0]);
                acc[c4 * 4 + 1] = fmaf(zk, w.y, acc[c4 * 4 + 1]);
                acc[c4 * 4 + 2] = fmaf(zk, w.z, acc[c4 * 4 + 2]);
                acc[c4 * 4 + 3] = fmaf(zk, w.w, acc[c4 * 4 + 3]);
            }
        }
    }
    float4* yo = (float4*)(d_Ybuf + row * HD);
#pragma unroll
    for (int c4 = 0; c4 < 16; c4++)
        yo[c4] = make_float4(acc[c4 * 4 + 0] * inv, acc[c4 * 4 + 1] * inv,
                             acc[c4 * 4 + 2] * inv, acc[c4 * 4 + 3] * inv);
}

// ---------------------------------------------------------------------------
// convN: msg = Y[src] + rel @ Wr + beff, max over edges + self, relu
// WRITE_Z: store z to d_Zbuf; POOL: per-graph max pooling via atomicMax
// ---------------------------------------------------------------------------
template <bool WRITE_Z, bool POOL>
__global__ __launch_bounds__(256) void convN_kernel(const float2* __restrict__ pos,
                                                    const float* __restrict__ Wfull) {
    __shared__ float s_z[32 * HD];
    __shared__ float s_red[64];
    int tid = threadIdx.x, lane = tid & 31, wid = tid >> 5;
    int f0 = lane * 2, f1 = f0 + 1;
    float wx0 = Wfull[64 * HD + f0], wx1 = Wfull[64 * HD + f1];
    float wy0 = Wfull[65 * HD + f0], wy1 = Wfull[65 * HD + f1];
    float be0 = d_beff[f0], be1 = d_beff[f1];
    int nodebase = blockIdx.x * 32 + wid * 4;

    for (int it = 0; it < 4; it++) {
        int node = nodebase + it;
        float2 pi = pos[node];
        float2 ys = *(const float2*)(d_Ybuf + node * HD + f0);
        float m0 = ys.x + be0, m1 = ys.y + be1;   // self edge
        int jj = 0; float px = 0.f, py = 0.f;
        if (lane < KNN) {
            jj = d_knn[node * KNN + lane];
            float2 pj = pos[jj];
            px = pj.x; py = pj.y;
        }
#pragma unroll
        for (int e = 0; e < KNN; e++) {
            int j = __shfl_sync(FULLMASK, jj, e);
            float dx = __shfl_sync(FULLMASK, px, e) - pi.x;
            float dy = __shfl_sync(FULLMASK, py, e) - pi.y;
            float2 yv = *(const float2*)(d_Ybuf + j * HD + f0);
            m0 = fmaxf(m0, fmaf(dx, wx0, fmaf(dy, wy0, yv.x + be0)));
            m1 = fmaxf(m1, fmaf(dx, wx1, fmaf(dy, wy1, yv.y + be1)));
        }
        float z0 = fmaxf(m0, 0.f), z1 = fmaxf(m1, 0.f);
        if (WRITE_Z)
            *(float2*)&d_Zbuf[node * HD + f0] = make_float2(z0, z1);
        int r = wid * 4 + it;
        s_z[r * HD + f0] = z0;
        s_z[r * HD + f1] = z1;
    }
    __syncthreads();
    block_stats(s_z, s_red, blockIdx.x);
    if (POOL) {
        if (tid < HD) {
            float m = s_z[tid];
#pragma unroll
            for (int r = 1; r < 32; r++) m = fmaxf(m, s_z[r * HD + tid]);
            int g = blockIdx.x >> 6;   // 64 blocks per graph
            atomicMax(&d_pool[g * HD + tid], __float_as_int(m));
        }
    }
}

// ---------------------------------------------------------------------------
// head: normalize pooled max (h = (poolmax - mean)*inv), then MLP -> out[64,2]
// ---------------------------------------------------------------------------
__global__ __launch_bounds__(128) void head_kernel(const float* __restrict__ Wl1,
                                                   const float* __restrict__ bl1,
                                                   const float* __restrict__ Wl2,
                                                   const float* __restrict__ bl2,
                                                   float* __restrict__ out) {
    __shared__ float hm[BGR * HD];
    __shared__ float t1[BGR * HD];
    int tid = threadIdx.x;
    float inv = d_scaleInv;
    for (int i = tid; i < BGR * HD; i += 128) {
        int f = i & 63;
        hm[i] = (__int_as_float(d_pool[i]) - d_mean[f]) * inv;
    }
    __syncthreads();

    int g = tid >> 1, half = tid & 1;
    float acc[32];
#pragma unroll
    for (int c = 0; c < 32; c++) acc[c] = bl1[half * 32 + c];
    for (int k = 0; k < HD; k++) {
        float h = hm[g * HD + k];
        const float* wrow = Wl1 + k * HD + half * 32;
#pragma unroll
        for (int c = 0; c < 32; c++) acc[c] = fmaf(h, wrow[c], acc[c]);
    }
#pragma unroll
    for (int c = 0; c < 32; c++) t1[g * HD + half * 32 + c] = fmaxf(acc[c], 0.f);
    __syncthreads();

    int gg = tid >> 1, o = tid & 1;
    float s = bl2[o];
    for (int k = 0; k < HD; k++) s = fmaf(t1[gg * HD + k], Wl2[k * 2 + o], s);
    out[gg * 2 + o] = s;
}

// ---------------------------------------------------------------------------
// launch
// ---------------------------------------------------------------------------
extern "C" void kernel_launch(void* const* d_in, const int* in_sizes, int n_in,
                              void* d_out, int out_size) {
    const float2* pos = (const float2*)d_in[0];
    // d_in[1] = batch (unused; graphs are contiguous 2048-point blocks)
    const float* W1  = (const float*)d_in[2];
    const float* b1  = (const float*)d_in[3];
    const float* W2  = (const float*)d_in[4];
    const float* b2  = (const float*)d_in[5];
    const float* W3  = (const float*)d_in[6];
    const float* b3  = (const float*)d_in[7];
    const float* Wl1 = (const float*)d_in[8];
    const float* bl1 = (const float*)d_in[9];
    const float* Wl2 = (const float*)d_in[10];
    const float* bl2 = (const float*)d_in[11];
    float* out = (float*)d_out;

    init_kernel<<<16, 256>>>();
    reorder_kernel<<<BGR, 256>>>(pos);
    knn_kernel<<<BGR * 8, 256>>>(pos);

    // layer 1
    conv1_kernel<<<CONV_BLOCKS, 256>>>(pos, W1, b1);
    reduce_kernel<<<64, 128>>>();
    stats_kernel<<<1, 64>>>(W2, b2);

    // layer 2
    gemm_kernel<<<NPTS / 128, 128>>>(W2);
    convN_kernel<true, false><<<CONV_BLOCKS, 256>>>(pos, W2);
    reduce_kernel<<<64, 128>>>();
    stats_kernel<<<1, 64>>>(W3, b3);

    // layer 3 (pools directly, no Z write)
    gemm_kernel<<<NPTS / 128, 128>>>(W3);
    convN_kernel<false, true><<<CONV_BLOCKS, 256>>>(pos, W3);
    reduce_kernel<<<64, 128>>>();
    stats_kernel<<<1, 64>>>(nullptr, nullptr);

    head_kernel<<<1, 128>>>(Wl1, bl1, Wl2, bl2, out);
}

// round 2
// speedup vs baseline: 1.0465x; 1.0465x over previous
#include <cuda_runtime.h>

#define NPTS 131072
#define BGR  64
#define NPG  2048
#define KNN  10
#define HD   64
#define CONV_BLOCKS (NPTS / 32)      // 4096
#define FULLMASK 0xffffffffu
#define PAIRNORM_EPS 1e-5f

// spatial grid for kNN
#define GDIM  64
#define NCELL (GDIM * GDIM)          // 4096
#define XMIN  (-5.0f)
#define CELL  0.15625f               // 10/64
#define INVCELL 6.4f

// ---------------------------------------------------------------------------
// Device scratch (static — no allocations allowed)
// ---------------------------------------------------------------------------
__device__ float2 d_spos[NPTS];             // positions sorted by cell (per graph)
__device__ int    d_sidx[NPTS];             // original local index for each sorted slot
__device__ int    d_cellstart[BGR * (NCELL + 1)];
__device__ int    d_knn[NPTS * KNN];        // global neighbor indices
__device__ float  d_Zbuf[NPTS * HD];        // raw relu(conv) output z
__device__ float  d_Ybuf[NPTS * HD];        // z @ Wx * invscale
__device__ float  d_part[CONV_BLOCKS * 65]; // per-block stats partials
__device__ float  d_part2[64 * 65];         // stage-2 partials
__device__ float  d_mean[HD];
__device__ float  d_scaleInv;
__device__ float  d_beff[HD];
__device__ int    d_pool[BGR * HD];         // pooled max (float bits, z>=0)

// ---------------------------------------------------------------------------
// init: zero the pool accumulator (re-zeroed every graph replay)
// ---------------------------------------------------------------------------
__global__ void init_kernel() {
    int i = blockIdx.x * blockDim.x + threadIdx.x;
    if (i < BGR * HD) d_pool[i] = 0;
}

// ---------------------------------------------------------------------------
// reorder: per-graph counting sort by 64x64 cell id (row-major).
// Produces CSR cell lists + sorted positions/indices. Within-cell order is
// nondeterministic (atomics) but the final kNN output is order-independent
// (lexicographic (d2, idx) selection), so kernel output stays deterministic.
// ---------------------------------------------------------------------------
__global__ __launch_bounds__(256) void reorder_kernel(const float2* __restrict__ pos) {
    __shared__ int hist[NCELL];               // 16 KB
    __shared__ unsigned short skey[NPG];      // 4 KB
    __shared__ int scanbuf[256];
    int g = blockIdx.x;
    int tid = threadIdx.x;
    int base = g * NPG;

    for (int c = tid; c < NCELL; c += 256) hist[c] = 0;
    __syncthreads();

    for (int t = tid; t < NPG; t += 256) {
        float2 p = pos[base + t];
        int cx = (int)((p.x - XMIN) * INVCELL);
        int cy = (int)((p.y - XMIN) * INVCELL);
        cx = cx < 0 ? 0 : (cx > GDIM - 1 ? GDIM - 1 : cx);
        cy = cy < 0 ? 0 : (cy > GDIM - 1 ? GDIM - 1 : cy);
        unsigned key = (unsigned)(cy * GDIM + cx);
        skey[t] = (unsigned short)key;
        atomicAdd(&hist[key], 1);
    }
    __syncthreads();

    // exclusive scan over 4096 cells: 256 threads x 16 cells each
    int cb = tid * 16;
    int loc[16];
    int tot = 0;
#pragma unroll
    for (int i = 0; i < 16; i++) { loc[i] = hist[cb + i]; tot += loc[i]; }
    scanbuf[tid] = tot;
    __syncthreads();
    for (int off = 1; off < 256; off <<= 1) {
        int add = 0;
        if (tid >= off) add = scanbuf[tid - off];
        __syncthreads();
        scanbuf[tid] += add;
        __syncthreads();
    }
    int run = scanbuf[tid] - tot;
#pragma unroll
    for (int i = 0; i < 16; i++) {
        hist[cb + i] = run;
        run += loc[i];
    }
    __syncthreads();

    // save cell starts to global before scatter destroys them
    int* cs = d_cellstart + g * (NCELL + 1);
    for (int c = tid; c < NCELL; c += 256) cs[c] = hist[c];
    if (tid == 0) cs[NCELL] = NPG;
    __syncthreads();

    for (int t = tid; t < NPG; t += 256) {
        int key = skey[t];
        int rank = atomicAdd(&hist[key], 1);
        d_spos[base + rank] = pos[base + t];
        d_sidx[base + rank] = t;
    }
}

// ---------------------------------------------------------------------------
// kNN: expanding-ring grid search, exact top-10 by lexicographic (d2, idx).
// d2 uses __fmul_rn/__fadd_rn to match the reference bit-exactly; pruning is
// conservative (distance to scanned-square boundary, squared with slack).
// ---------------------------------------------------------------------------
#define INS2(da, db, ia, ib) { \
    if ((db < da) || (db == da && ib < ia)) { \
        float _t = da; da = db; db = _t; int _u = ia; ia = ib; ib = _u; } }

__global__ __launch_bounds__(1024) void knn_kernel() {
    __shared__ float2 spos[NPG];          // 16 KB
    __shared__ int    sidx[NPG];          // 8 KB
    __shared__ int    scs[NCELL + 1];     // 16 KB
    int g = blockIdx.x >> 1;
    int half = blockIdx.x & 1;
    int base = g * NPG;
    int tid = threadIdx.x;

    for (int t = tid; t < NPG; t += 1024) { spos[t] = d_spos[base + t]; sidx[t] = d_sidx[base + t]; }
    const int* gcs = d_cellstart + g * (NCELL + 1);
    for (int c = tid; c < NCELL + 1; c += 1024) scs[c] = gcs[c];
    __syncthreads();

    int r = half * 1024 + tid;
    float2 q = spos[r];
    int qi = sidx[r];

    int cx = (int)((q.x - XMIN) * INVCELL);
    int cy = (int)((q.y - XMIN) * INVCELL);
    cx = cx < 0 ? 0 : (cx > GDIM - 1 ? GDIM - 1 : cx);
    cy = cy < 0 ? 0 : (cy > GDIM - 1 ? GDIM - 1 : cy);

    const float INF = __int_as_float(0x7f800000);
    float s0 = INF, s1 = INF, s2 = INF, s3 = INF, s4 = INF;
    float s5 = INF, s6 = INF, s7 = INF, s8 = INF, s9 = INF;
    int n0 = 0x7fffffff, n1 = n0, n2 = n0, n3 = n0, n4 = n0;
    int n5 = n0, n6 = n0, n7 = n0, n8 = n0, n9 = n0;

#define SCANCELL(CX, CY) { \
    int _c = (CY) * GDIM + (CX); \
    int _pe = scs[_c + 1]; \
    for (int _p = scs[_c]; _p < _pe; _p++) { \
        float2 cp = spos[_p]; \
        int oi = sidx[_p]; \
        float dx = q.x - cp.x; \
        float dy = q.y - cp.y; \
        float d2 = __fadd_rn(__fmul_rn(dx, dx), __fmul_rn(dy, dy)); \
        if ((d2 < s9 || (d2 == s9 && oi < n9)) && oi != qi) { \
            s9 = d2; n9 = oi; \
            INS2(s8, s9, n8, n9); INS2(s7, s8, n7, n8); INS2(s6, s7, n6, n7); \
            INS2(s5, s6, n5, n6); INS2(s4, s5, n4, n5); INS2(s3, s4, n3, n4); \
            INS2(s2, s3, n2, n3); INS2(s1, s2, n1, n2); INS2(s0, s1, n0, n1); \
        } } }

    for (int R = 0; R < GDIM; R++) {
        if (R >= 1) {
            // scanned region covers cells [cx-(R-1), cx+(R-1)] x [cy-(R-1), cy+(R-1)]
            float lox = XMIN + (float)(cx - R + 1) * CELL;
            float hix = XMIN + (float)(cx + R) * CELL;
            float loy = XMIN + (float)(cy - R + 1) * CELL;
            float hiy = XMIN + (float)(cy + R) * CELL;
            float bnd = fminf(fminf(q.x - lox, hix - q.x), fminf(q.y - loy, hiy - q.y));
            if (bnd > 0.f && bnd * bnd * 0.9999f > s9) break;
        }
        if (R == 0) {
            SCANCELL(cx, cy);
        } else {
            int x0 = cx - R < 0 ? 0 : cx - R;
            int x1 = cx + R > GDIM - 1 ? GDIM - 1 : cx + R;
            if (cy - R >= 0)        for (int xx = x0; xx <= x1; xx++) SCANCELL(xx, cy - R);
            if (cy + R <= GDIM - 1) for (int xx = x0; xx <= x1; xx++) SCANCELL(xx, cy + R);
            int y0 = cy - R + 1 < 0 ? 0 : cy - R + 1;
            int y1 = cy + R - 1 > GDIM - 1 ? GDIM - 1 : cy + R - 1;
            if (cx - R >= 0)        for (int yy = y0; yy <= y1; yy++) SCANCELL(cx - R, yy);
            if (cx + R <= GDIM - 1) for (int yy = y0; yy <= y1; yy++) SCANCELL(cx + R, yy);
        }
    }

    int* op = d_knn + (base + qi) * KNN;
    op[0] = base + n0; op[1] = base + n1; op[2] = base + n2; op[3] = base + n3;
    op[4] = base + n4; op[5] = base + n5; op[6] = base + n6; op[7] = base + n7;
    op[8] = base + n8; op[9] = base + n9;
}

// ---------------------------------------------------------------------------
// deterministic block stats from s_z[32][HD] -> d_part[block][65]
// ---------------------------------------------------------------------------
__device__ __forceinline__ void block_stats(const float* s_z, float* s_red, int blockId) {
    int tid = threadIdx.x;
    if (tid < HD) {
        float s = 0.f, sq = 0.f;
#pragma unroll
        for (int r = 0; r < 32; r++) {
            float v = s_z[r * HD + tid];
            s += v;
            sq = fmaf(v, v, sq);
        }
        d_part[blockId * 65 + tid] = s;
        s_red[tid] = sq;
    }
    __syncthreads();
    if (tid < 32) {
        float v = s_red[tid] + s_red[tid + 32];
#pragma unroll
        for (int off = 16; off > 0; off >>= 1)
            v += __shfl_down_sync(FULLMASK, v, off);
        if (tid == 0) d_part[blockId * 65 + 64] = v;
    }
}

// ---------------------------------------------------------------------------
// conv1: msg = rel @ W1 + b1, max over 10 knn edges + self(rel=0 -> b1), relu
// ---------------------------------------------------------------------------
__global__ __launch_bounds__(256) void conv1_kernel(const float2* __restrict__ pos,
                                                    const float* __restrict__ W1,
                                                    const float* __restrict__ b1) {
    __shared__ float s_z[32 * HD];
    __shared__ float s_red[64];
    int tid = threadIdx.x, lane = tid & 31, wid = tid >> 5;
    int f0 = lane * 2, f1 = f0 + 1;
    float wx0 = W1[f0],      wx1 = W1[f1];
    float wy0 = W1[HD + f0], wy1 = W1[HD + f1];
    float bb0 = b1[f0],      bb1 = b1[f1];
    int nodebase = blockIdx.x * 32 + wid * 4;

    for (int it = 0; it < 4; it++) {
        int node = nodebase + it;
        float2 pi = pos[node];
        float m0 = bb0, m1 = bb1;                    // self edge: rel = 0
        float px = 0.f, py = 0.f;
        if (lane < KNN) {
            int jj = d_knn[node * KNN + lane];
            float2 pj = pos[jj];
            px = pj.x; py = pj.y;
        }
#pragma unroll
        for (int e = 0; e < KNN; e++) {
            float dx = __shfl_sync(FULLMASK, px, e) - pi.x;
            float dy = __shfl_sync(FULLMASK, py, e) - pi.y;
            m0 = fmaxf(m0, fmaf(dx, wx0, fmaf(dy, wy0, bb0)));
            m1 = fmaxf(m1, fmaf(dx, wx1, fmaf(dy, wy1, bb1)));
        }
        float z0 = fmaxf(m0, 0.f), z1 = fmaxf(m1, 0.f);
        *(float2*)&d_Zbuf[node * HD + f0] = make_float2(z0, z1);
        int r = wid * 4 + it;
        s_z[r * HD + f0] = z0;
        s_z[r * HD + f1] = z1;
    }
    __syncthreads();
    block_stats(s_z, s_red, blockIdx.x);
}

// ---------------------------------------------------------------------------
// stage-2 reduce: d_part[4096][65] -> d_part2[64][65]
// ---------------------------------------------------------------------------
__global__ __launch_bounds__(128) void reduce_kernel() {
    __shared__ float s_sq[16];
    int tid = threadIdx.x;
    int rbase = blockIdx.x * 64;
    if (tid < 64) {
        float s = 0.f;
        for (int r = 0; r < 64; r++) s += d_part[(rbase + r) * 65 + tid];
        d_part2[blockIdx.x * 65 + tid] = s;
    } else if (tid < 80) {
        int j = tid - 64;
        float s = 0.f;
        for (int r = 0; r < 4; r++) s += d_part[(rbase + j * 4 + r) * 65 + 64];
        s_sq[j] = s;
    }
    __syncthreads();
    if (tid == 64) {
        float s = 0.f;
        for (int j = 0; j < 16; j++) s += s_sq[j];
        d_part2[blockIdx.x * 65 + 64] = s;
    }
}

// ---------------------------------------------------------------------------
// final stats: mean, inv scale, folded effective bias
// ---------------------------------------------------------------------------
__global__ __launch_bounds__(64) void stats_kernel(const float* __restrict__ Wnext,
                                                   const float* __restrict__ bnext) {
    __shared__ float smean[64];
    int tid = threadIdx.x;
    float s = 0.f;
    for (int r = 0; r < 64; r++) s += d_part2[r * 65 + tid];
    float mean = s * (1.0f / (float)NPTS);
    smean[tid] = mean;
    d_mean[tid] = mean;
    __syncthreads();
    if (tid == 0) {
        float sq = 0.f;
        for (int r = 0; r < 64; r++) sq += d_part2[r * 65 + 64];
        float ms = 0.f;
        for (int f = 0; f < 64; f++) ms = fmaf(smean[f], smean[f], ms);
        float denom = sq * (1.0f / (float)NPTS) - ms;
        d_scaleInv = 1.0f / sqrtf(PAIRNORM_EPS + denom);
    }
    __syncthreads();
    if (Wnext != nullptr) {
        float acc = 0.f;
        for (int k = 0; k < 64; k++) acc = fmaf(smean[k], Wnext[k * HD + tid], acc);
        d_beff[tid] = bnext[tid] - d_scaleInv * acc;
    }
}

// ---------------------------------------------------------------------------
// GEMM: d_Ybuf = d_Zbuf @ W[0:64,:] * d_scaleInv     (131072 x 64 x 64)
// ---------------------------------------------------------------------------
__global__ __launch_bounds__(128) void gemm_kernel(const float* __restrict__ W) {
    __shared__ float4 sw[1024];
    int tid = threadIdx.x;
    const float4* W4 = (const float4*)W;
    for (int i = tid; i < 1024; i += 128) sw[i] = W4[i];
    float inv = d_scaleInv;
    __syncthreads();

    int row = blockIdx.x * 128 + tid;
    const float4* zr = (const float4*)(d_Zbuf + row * HD);
    float acc[64];
#pragma unroll
    for (int c = 0; c < 64; c++) acc[c] = 0.f;

#pragma unroll 1
    for (int k4 = 0; k4 < 16; k4++) {
        float4 z4 = zr[k4];
#pragma unroll
        for (int kk = 0; kk < 4; kk++) {
            float zk = (kk == 0) ? z4.x : (kk == 1) ? z4.y : (kk == 2) ? z4.z : z4.w;
            int kI = k4 * 4 + kk;
#pragma unroll
            for (int c4 = 0; c4 < 16; c4++) {
                float4 w = sw[kI * 16 + c4];
                acc[c4 * 4 + 0] = fmaf(zk, w.x, acc[c4 * 4 + 0]);
                acc[c4 * 4 + 1] = fmaf(zk, w.y, acc[c4 * 4 + 1]);
                acc[c4 * 4 + 2] = fmaf(zk, w.z, acc[c4 * 4 + 2]);
                acc[c4 * 4 + 3] = fmaf(zk, w.w, acc[c4 * 4 + 3]);
            }
        }
    }
    float4* yo = (float4*)(d_Ybuf + row * HD);
#pragma unroll
    for (int c4 = 0; c4 < 16; c4++)
        yo[c4] = make_float4(acc[c4 * 4 + 0] * inv, acc[c4 * 4 + 1] * inv,
                             acc[c4 * 4 + 2] * inv, acc[c4 * 4 + 3] * inv);
}

// ---------------------------------------------------------------------------
// convN: msg = Y[src] + rel @ Wr + beff, max over edges + self, relu
// ---------------------------------------------------------------------------
template <bool WRITE_Z, bool POOL>
__global__ __launch_bounds__(256) void convN_kernel(const float2* __restrict__ pos,
                                                    const float* __restrict__ Wfull) {
    __shared__ float s_z[32 * HD];
    __shared__ float s_red[64];
    int tid = threadIdx.x, lane = tid & 31, wid = tid >> 5;
    int f0 = lane * 2, f1 = f0 + 1;
    float wx0 = Wfull[64 * HD + f0], wx1 = Wfull[64 * HD + f1];
    float wy0 = Wfull[65 * HD + f0], wy1 = Wfull[65 * HD + f1];
    float be0 = d_beff[f0], be1 = d_beff[f1];
    int nodebase = blockIdx.x * 32 + wid * 4;

    for (int it = 0; it < 4; it++) {
        int node = nodebase + it;
        float2 pi = pos[node];
        float2 ys = *(const float2*)(d_Ybuf + node * HD + f0);
        float m0 = ys.x + be0, m1 = ys.y + be1;   // self edge
        int jj = 0; float px = 0.f, py = 0.f;
        if (lane < KNN) {
            jj = d_knn[node * KNN + lane];
            float2 pj = pos[jj];
            px = pj.x; py = pj.y;
        }
#pragma unroll
        for (int e = 0; e < KNN; e++) {
            int j = __shfl_sync(FULLMASK, jj, e);
            float dx = __shfl_sync(FULLMASK, px, e) - pi.x;
            float dy = __shfl_sync(FULLMASK, py, e) - pi.y;
            float2 yv = *(const float2*)(d_Ybuf + j * HD + f0);
            m0 = fmaxf(m0, fmaf(dx, wx0, fmaf(dy, wy0, yv.x + be0)));
            m1 = fmaxf(m1, fmaf(dx, wx1, fmaf(dy, wy1, yv.y + be1)));
        }
        float z0 = fmaxf(m0, 0.f), z1 = fmaxf(m1, 0.f);
        if (WRITE_Z)
            *(float2*)&d_Zbuf[node * HD + f0] = make_float2(z0, z1);
        int r = wid * 4 + it;
        s_z[r * HD + f0] = z0;
        s_z[r * HD + f1] = z1;
    }
    __syncthreads();
    block_stats(s_z, s_red, blockIdx.x);
    if (POOL) {
        if (tid < HD) {
            float m = s_z[tid];
#pragma unroll
            for (int r = 1; r < 32; r++) m = fmaxf(m, s_z[r * HD + tid]);
            int g = blockIdx.x >> 6;   // 64 blocks per graph
            atomicMax(&d_pool[g * HD + tid], __float_as_int(m));
        }
    }
}

// ---------------------------------------------------------------------------
// head: normalize pooled max, then MLP -> out[64,2]
// ---------------------------------------------------------------------------
__global__ __launch_bounds__(128) void head_kernel(const float* __restrict__ Wl1,
                                                   const float* __restrict__ bl1,
                                                   const float* __restrict__ Wl2,
                                                   const float* __restrict__ bl2,
                                                   float* __restrict__ out) {
    __shared__ float hm[BGR * HD];
    __shared__ float t1[BGR * HD];
    int tid = threadIdx.x;
    float inv = d_scaleInv;
    for (int i = tid; i < BGR * HD; i += 128) {
        int f = i & 63;
        hm[i] = (__int_as_float(d_pool[i]) - d_mean[f]) * inv;
    }
    __syncthreads();

    int g = tid >> 1, half = tid & 1;
    float acc[32];
#pragma unroll
    for (int c = 0; c < 32; c++) acc[c] = bl1[half * 32 + c];
    for (int k = 0; k < HD; k++) {
        float h = hm[g * HD + k];
        const float* wrow = Wl1 + k * HD + half * 32;
#pragma unroll
        for (int c = 0; c < 32; c++) acc[c] = fmaf(h, wrow[c], acc[c]);
    }
#pragma unroll
    for (int c = 0; c < 32; c++) t1[g * HD + half * 32 + c] = fmaxf(acc[c], 0.f);
    __syncthreads();

    int gg = tid >> 1, o = tid & 1;
    float s = bl2[o];
    for (int k = 0; k < HD; k++) s = fmaf(t1[gg * HD + k], Wl2[k * 2 + o], s);
    out[gg * 2 + o] = s;
}

// ---------------------------------------------------------------------------
// launch
// ---------------------------------------------------------------------------
extern "C" void kernel_launch(void* const* d_in, const int* in_sizes, int n_in,
                              void* d_out, int out_size) {
    const float2* pos = (const float2*)d_in[0];
    const float* W1  = (const float*)d_in[2];
    const float* b1  = (const float*)d_in[3];
    const float* W2  = (const float*)d_in[4];
    const float* b2  = (const float*)d_in[5];
    const float* W3  = (const float*)d_in[6];
    const float* b3  = (const float*)d_in[7];
    const float* Wl1 = (const float*)d_in[8];
    const float* bl1 = (const float*)d_in[9];
    const float* Wl2 = (const float*)d_in[10];
    const float* bl2 = (const float*)d_in[11];
    float* out = (float*)d_out;

    init_kernel<<<16, 256>>>();
    reorder_kernel<<<BGR, 256>>>(pos);
    knn_kernel<<<BGR * 2, 1024>>>();

    // layer 1
    conv1_kernel<<<CONV_BLOCKS, 256>>>(pos, W1, b1);
    reduce_kernel<<<64, 128>>>();
    stats_kernel<<<1, 64>>>(W2, b2);

    // layer 2
    gemm_kernel<<<NPTS / 128, 128>>>(W2);
    convN_kernel<true, false><<<CONV_BLOCKS, 256>>>(pos, W2);
    reduce_kernel<<<64, 128>>>();
    stats_kernel<<<1, 64>>>(W3, b3);

    // layer 3 (pools directly, no Z write)
    gemm_kernel<<<NPTS / 128, 128>>>(W3);
    convN_kernel<false, true><<<CONV_BLOCKS, 256>>>(pos, W3);
    reduce_kernel<<<64, 128>>>();
    stats_kernel<<<1, 64>>>(nullptr, nullptr);

    head_kernel<<<1, 128>>>(Wl1, bl1, Wl2, bl2, out);
}

// round 3
// speedup vs baseline: 1.1720x; 1.1200x over previous
#include <cuda_runtime.h>

#define NPTS 131072
#define BGR  64
#define NPG  2048
#define KNN  10
#define HD   64
#define CONV_BLOCKS (NPTS / 32)      // 4096
#define FULLMASK 0xffffffffu
#define PAIRNORM_EPS 1e-5f

// spatial grid for kNN
#define GDIM  64
#define NCELL (GDIM * GDIM)          // 4096
#define XMIN  (-5.0f)
#define CELL  0.15625f               // 10/64
#define INVCELL 6.4f

// ---------------------------------------------------------------------------
// Device scratch
// ---------------------------------------------------------------------------
__device__ float2 d_spos[NPTS];
__device__ int    d_sidx[NPTS];
__device__ int    d_cellstart[BGR * (NCELL + 1)];
__device__ int    d_knn[NPTS * KNN];
__device__ float  d_Ya[NPTS * HD];          // Yraw for layer 2 gather
__device__ float  d_Yb[NPTS * HD];          // Yraw for layer 3 gather
__device__ float  d_part[CONV_BLOCKS * 65];
__device__ float  d_part2[64 * 65];
__device__ float  d_mean[HD];
__device__ float  d_scaleInv;
__device__ float  d_beff[HD];
__device__ int    d_pool[BGR * HD];
__device__ unsigned d_rc;                   // redstat ticket counter (self-resetting)

// ---------------------------------------------------------------------------
// reorder: per-graph counting sort by 64x64 cell id. Block 0 also zeroes pool.
// Within-cell order is nondeterministic (atomics) but kNN output is
// order-independent (lexicographic (d2, idx) selection) -> deterministic.
// ---------------------------------------------------------------------------
__global__ __launch_bounds__(256) void reorder_kernel(const float2* __restrict__ pos) {
    __shared__ int hist[NCELL];
    __shared__ unsigned short skey[NPG];
    __shared__ int scanbuf[256];
    int g = blockIdx.x;
    int tid = threadIdx.x;
    int base = g * NPG;

    if (g == 0) {
        for (int i = tid; i < BGR * HD; i += 256) d_pool[i] = 0;
    }

    for (int c = tid; c < NCELL; c += 256) hist[c] = 0;
    __syncthreads();

    for (int t = tid; t < NPG; t += 256) {
        float2 p = pos[base + t];
        int cx = (int)((p.x - XMIN) * INVCELL);
        int cy = (int)((p.y - XMIN) * INVCELL);
        cx = cx < 0 ? 0 : (cx > GDIM - 1 ? GDIM - 1 : cx);
        cy = cy < 0 ? 0 : (cy > GDIM - 1 ? GDIM - 1 : cy);
        unsigned key = (unsigned)(cy * GDIM + cx);
        skey[t] = (unsigned short)key;
        atomicAdd(&hist[key], 1);
    }
    __syncthreads();

    int cb = tid * 16;
    int loc[16];
    int tot = 0;
#pragma unroll
    for (int i = 0; i < 16; i++) { loc[i] = hist[cb + i]; tot += loc[i]; }
    scanbuf[tid] = tot;
    __syncthreads();
    for (int off = 1; off < 256; off <<= 1) {
        int add = 0;
        if (tid >= off) add = scanbuf[tid - off];
        __syncthreads();
        scanbuf[tid] += add;
        __syncthreads();
    }
    int run = scanbuf[tid] - tot;
#pragma unroll
    for (int i = 0; i < 16; i++) {
        hist[cb + i] = run;
        run += loc[i];
    }
    __syncthreads();

    int* cs = d_cellstart + g * (NCELL + 1);
    for (int c = tid; c < NCELL; c += 256) cs[c] = hist[c];
    if (tid == 0) cs[NCELL] = NPG;
    __syncthreads();

    for (int t = tid; t < NPG; t += 256) {
        int key = skey[t];
        int rank = atomicAdd(&hist[key], 1);
        d_spos[base + rank] = pos[base + t];
        d_sidx[base + rank] = t;
    }
}

// ---------------------------------------------------------------------------
// kNN: expanding-ring grid search, exact top-10 by lexicographic (d2, idx).
// ---------------------------------------------------------------------------
#define INS2(da, db, ia, ib) { \
    if ((db < da) || (db == da && ib < ia)) { \
        float _t = da; da = db; db = _t; int _u = ia; ia = ib; ib = _u; } }

__global__ __launch_bounds__(1024) void knn_kernel() {
    __shared__ float2 spos[NPG];
    __shared__ int    sidx[NPG];
    __shared__ int    scs[NCELL + 1];
    int g = blockIdx.x >> 1;
    int half = blockIdx.x & 1;
    int base = g * NPG;
    int tid = threadIdx.x;

    for (int t = tid; t < NPG; t += 1024) { spos[t] = d_spos[base + t]; sidx[t] = d_sidx[base + t]; }
    const int* gcs = d_cellstart + g * (NCELL + 1);
    for (int c = tid; c < NCELL + 1; c += 1024) scs[c] = gcs[c];
    __syncthreads();

    int r = half * 1024 + tid;
    float2 q = spos[r];
    int qi = sidx[r];

    int cx = (int)((q.x - XMIN) * INVCELL);
    int cy = (int)((q.y - XMIN) * INVCELL);
    cx = cx < 0 ? 0 : (cx > GDIM - 1 ? GDIM - 1 : cx);
    cy = cy < 0 ? 0 : (cy > GDIM - 1 ? GDIM - 1 : cy);

    const float INF = __int_as_float(0x7f800000);
    float s0 = INF, s1 = INF, s2 = INF, s3 = INF, s4 = INF;
    float s5 = INF, s6 = INF, s7 = INF, s8 = INF, s9 = INF;
    int n0 = 0x7fffffff, n1 = n0, n2 = n0, n3 = n0, n4 = n0;
    int n5 = n0, n6 = n0, n7 = n0, n8 = n0, n9 = n0;

#define SCANCELL(CX, CY) { \
    int _c = (CY) * GDIM + (CX); \
    int _pe = scs[_c + 1]; \
    for (int _p = scs[_c]; _p < _pe; _p++) { \
        float2 cp = spos[_p]; \
        int oi = sidx[_p]; \
        float dx = q.x - cp.x; \
        float dy = q.y - cp.y; \
        float d2 = __fadd_rn(__fmul_rn(dx, dx), __fmul_rn(dy, dy)); \
        if ((d2 < s9 || (d2 == s9 && oi < n9)) && oi != qi) { \
            s9 = d2; n9 = oi; \
            INS2(s8, s9, n8, n9); INS2(s7, s8, n7, n8); INS2(s6, s7, n6, n7); \
            INS2(s5, s6, n5, n6); INS2(s4, s5, n4, n5); INS2(s3, s4, n3, n4); \
            INS2(s2, s3, n2, n3); INS2(s1, s2, n1, n2); INS2(s0, s1, n0, n1); \
        } } }

    for (int R = 0; R < GDIM; R++) {
        if (R >= 1) {
            float lox = XMIN + (float)(cx - R + 1) * CELL;
            float hix = XMIN + (float)(cx + R) * CELL;
            float loy = XMIN + (float)(cy - R + 1) * CELL;
            float hiy = XMIN + (float)(cy + R) * CELL;
            float bnd = fminf(fminf(q.x - lox, hix - q.x), fminf(q.y - loy, hiy - q.y));
            if (bnd > 0.f && bnd * bnd * 0.9999f > s9) break;
        }
        if (R == 0) {
            SCANCELL(cx, cy);
        } else {
            int x0 = cx - R < 0 ? 0 : cx - R;
            int x1 = cx + R > GDIM - 1 ? GDIM - 1 : cx + R;
            if (cy - R >= 0)        for (int xx = x0; xx <= x1; xx++) SCANCELL(xx, cy - R);
            if (cy + R <= GDIM - 1) for (int xx = x0; xx <= x1; xx++) SCANCELL(xx, cy + R);
            int y0 = cy - R + 1 < 0 ? 0 : cy - R + 1;
            int y1 = cy + R - 1 > GDIM - 1 ? GDIM - 1 : cy + R - 1;
            if (cx - R >= 0)        for (int yy = y0; yy <= y1; yy++) SCANCELL(cx - R, yy);
            if (cx + R <= GDIM - 1) for (int yy = y0; yy <= y1; yy++) SCANCELL(cx + R, yy);
        }
    }

    int* op = d_knn + (base + qi) * KNN;
    op[0] = base + n0; op[1] = base + n1; op[2] = base + n2; op[3] = base + n3;
    op[4] = base + n4; op[5] = base + n5; op[6] = base + n6; op[7] = base + n7;
    op[8] = base + n8; op[9] = base + n9;
}

// ---------------------------------------------------------------------------
// block stats from padded s_z[32][65] -> d_part[block][65]
// ---------------------------------------------------------------------------
__device__ __forceinline__ void block_stats(const float* s_z, float* s_red, int blockId) {
    int tid = threadIdx.x;
    if (tid < HD) {
        float s = 0.f, sq = 0.f;
#pragma unroll
        for (int r = 0; r < 32; r++) {
            float v = s_z[r * 65 + tid];
            s += v;
            sq = fmaf(v, v, sq);
        }
        d_part[blockId * 65 + tid] = s;
        s_red[tid] = sq;
    }
    __syncthreads();
    if (tid < 32) {
        float v = s_red[tid] + s_red[tid + 32];
#pragma unroll
        for (int off = 16; off > 0; off >>= 1)
            v += __shfl_down_sync(FULLMASK, v, off);
        if (tid == 0) d_part[blockId * 65 + 64] = v;
    }
}

// ---------------------------------------------------------------------------
// epilogue GEMM: Yout[node][:] = s_z(32x64, pad65) @ sW(64x64)
// thread: row = tid&31, colgroup = tid>>5 (8 cols each)
// ---------------------------------------------------------------------------
__device__ __forceinline__ void epilogue_gemm(const float* s_z, const float4* sW,
                                              float* Yout, int nodebase) {
    int tid = threadIdx.x;
    int row = tid & 31;
    int cg = tid >> 5;
    float4 a0 = make_float4(0.f, 0.f, 0.f, 0.f);
    float4 a1 = make_float4(0.f, 0.f, 0.f, 0.f);
    const float* zr = s_z + row * 65;
#pragma unroll 4
    for (int k = 0; k < 64; k++) {
        float zk = zr[k];
        float4 w0 = sW[k * 16 + cg * 2];
        float4 w1 = sW[k * 16 + cg * 2 + 1];
        a0.x = fmaf(zk, w0.x, a0.x); a0.y = fmaf(zk, w0.y, a0.y);
        a0.z = fmaf(zk, w0.z, a0.z); a0.w = fmaf(zk, w0.w, a0.w);
        a1.x = fmaf(zk, w1.x, a1.x); a1.y = fmaf(zk, w1.y, a1.y);
        a1.z = fmaf(zk, w1.z, a1.z); a1.w = fmaf(zk, w1.w, a1.w);
    }
    float4* yo = (float4*)(Yout + (nodebase + row) * HD + cg * 8);
    yo[0] = a0;
    yo[1] = a1;
}

// ---------------------------------------------------------------------------
// convA (layer 1): msg = rel @ W1 + b1, max + relu; epilogue Yraw2 = z @ W2x
// ---------------------------------------------------------------------------
__global__ __launch_bounds__(256) void convA_kernel(const float2* __restrict__ pos,
                                                    const float* __restrict__ W1,
                                                    const float* __restrict__ b1,
                                                    const float* __restrict__ W2) {
    __shared__ float  s_z[32 * 65];
    __shared__ float4 sW[1024];
    __shared__ float2 s_rel[8][KNN];
    __shared__ float  s_red[64];
    int tid = threadIdx.x, lane = tid & 31, wid = tid >> 5;
    int f0 = lane * 2, f1 = f0 + 1;
    float wx0 = W1[f0],      wx1 = W1[f1];
    float wy0 = W1[HD + f0], wy1 = W1[HD + f1];
    float bb0 = b1[f0],      bb1 = b1[f1];
    int nodebase = blockIdx.x * 32;

    const float4* W2x4 = (const float4*)W2;      // rows 0..63 of W2
    for (int i = tid; i < 1024; i += 256) sW[i] = W2x4[i];

    for (int it = 0; it < 4; it++) {
        int node = nodebase + wid * 4 + it;
        float2 pi = pos[node];
        __syncwarp();
        if (lane < KNN) {
            int jj = d_knn[node * KNN + lane];
            float2 pj = pos[jj];
            s_rel[wid][lane] = make_float2(pj.x - pi.x, pj.y - pi.y);
        }
        __syncwarp();
        float m0 = bb0, m1 = bb1;   // self edge rel=0
#pragma unroll
        for (int e = 0; e < KNN; e++) {
            float2 rel = s_rel[wid][e];
            m0 = fmaxf(m0, fmaf(rel.x, wx0, fmaf(rel.y, wy0, bb0)));
            m1 = fmaxf(m1, fmaf(rel.x, wx1, fmaf(rel.y, wy1, bb1)));
        }
        int r = wid * 4 + it;
        s_z[r * 65 + f0] = fmaxf(m0, 0.f);
        s_z[r * 65 + f1] = fmaxf(m1, 0.f);
    }
    __syncthreads();
    block_stats(s_z, s_red, blockIdx.x);
    __syncthreads();
    epilogue_gemm(s_z, sW, d_Ya, nodebase);
}

// ---------------------------------------------------------------------------
// convB (layer 2): msg = inv*Yraw[j] + rel @ Wr + beff, max + relu;
//                  epilogue Yraw3 = z @ W3x.  Reads d_Ya, writes d_Yb.
// ---------------------------------------------------------------------------
__global__ __launch_bounds__(256) void convB_kernel(const float2* __restrict__ pos,
                                                    const float* __restrict__ W2,
                                                    const float* __restrict__ W3) {
    __shared__ float  s_z[32 * 65];
    __shared__ float4 sW[1024];
    __shared__ float2 s_rel[8][KNN];
    __shared__ int    s_j[8][KNN];
    __shared__ float  s_red[64];
    int tid = threadIdx.x, lane = tid & 31, wid = tid >> 5;
    int f0 = lane * 2, f1 = f0 + 1;
    float wx0 = W2[64 * HD + f0], wx1 = W2[64 * HD + f1];
    float wy0 = W2[65 * HD + f0], wy1 = W2[65 * HD + f1];
    float be0 = d_beff[f0], be1 = d_beff[f1];
    float inv = d_scaleInv;
    int nodebase = blockIdx.x * 32;

    const float4* W3x4 = (const float4*)W3;
    for (int i = tid; i < 1024; i += 256) sW[i] = W3x4[i];

    for (int it = 0; it < 4; it++) {
        int node = nodebase + wid * 4 + it;
        float2 pi = pos[node];
        __syncwarp();
        if (lane < KNN) {
            int jj = d_knn[node * KNN + lane];
            float2 pj = pos[jj];
            s_rel[wid][lane] = make_float2(pj.x - pi.x, pj.y - pi.y);
            s_j[wid][lane] = jj;
        }
        __syncwarp();
        float2 ys = *(const float2*)(d_Ya + node * HD + f0);
        float m0 = fmaf(inv, ys.x, be0), m1 = fmaf(inv, ys.y, be1);   // self
#pragma unroll
        for (int e = 0; e < KNN; e++) {
            float2 rel = s_rel[wid][e];
            int j = s_j[wid][e];
            float2 yv = *(const float2*)(d_Ya + j * HD + f0);
            m0 = fmaxf(m0, fmaf(inv, yv.x, fmaf(rel.x, wx0, fmaf(rel.y, wy0, be0))));
            m1 = fmaxf(m1, fmaf(inv, yv.y, fmaf(rel.x, wx1, fmaf(rel.y, wy1, be1))));
        }
        int r = wid * 4 + it;
        s_z[r * 65 + f0] = fmaxf(m0, 0.f);
        s_z[r * 65 + f1] = fmaxf(m1, 0.f);
    }
    __syncthreads();
    block_stats(s_z, s_red, blockIdx.x);
    __syncthreads();
    epilogue_gemm(s_z, sW, d_Yb, nodebase);
}

// ---------------------------------------------------------------------------
// convC (layer 3): same gather (from d_Yb), stats + per-graph max pool.
// ---------------------------------------------------------------------------
__global__ __launch_bounds__(256) void convC_kernel(const float2* __restrict__ pos,
                                                    const float* __restrict__ W3) {
    __shared__ float  s_z[32 * 65];
    __shared__ float2 s_rel[8][KNN];
    __shared__ int    s_j[8][KNN];
    __shared__ float  s_red[64];
    int tid = threadIdx.x, lane = tid & 31, wid = tid >> 5;
    int f0 = lane * 2, f1 = f0 + 1;
    float wx0 = W3[64 * HD + f0], wx1 = W3[64 * HD + f1];
    float wy0 = W3[65 * HD + f0], wy1 = W3[65 * HD + f1];
    float be0 = d_beff[f0], be1 = d_beff[f1];
    float inv = d_scaleInv;
    int nodebase = blockIdx.x * 32;

    for (int it = 0; it < 4; it++) {
        int node = nodebase + wid * 4 + it;
        float2 pi = pos[node];
        __syncwarp();
        if (lane < KNN) {
            int jj = d_knn[node * KNN + lane];
            float2 pj = pos[jj];
            s_rel[wid][lane] = make_float2(pj.x - pi.x, pj.y - pi.y);
            s_j[wid][lane] = jj;
        }
        __syncwarp();
        float2 ys = *(const float2*)(d_Yb + node * HD + f0);
        float m0 = fmaf(inv, ys.x, be0), m1 = fmaf(inv, ys.y, be1);
#pragma unroll
        for (int e = 0; e < KNN; e++) {
            float2 rel = s_rel[wid][e];
            int j = s_j[wid][e];
            float2 yv = *(const float2*)(d_Yb + j * HD + f0);
            m0 = fmaxf(m0, fmaf(inv, yv.x, fmaf(rel.x, wx0, fmaf(rel.y, wy0, be0))));
            m1 = fmaxf(m1, fmaf(inv, yv.y, fmaf(rel.x, wx1, fmaf(rel.y, wy1, be1))));
        }
        int r = wid * 4 + it;
        s_z[r * 65 + f0] = fmaxf(m0, 0.f);
        s_z[r * 65 + f1] = fmaxf(m1, 0.f);
    }
    __syncthreads();
    block_stats(s_z, s_red, blockIdx.x);
    if (tid < HD) {
        float m = s_z[tid];
#pragma unroll
        for (int r = 1; r < 32; r++) m = fmaxf(m, s_z[r * 65 + tid]);
        int g = blockIdx.x >> 6;
        atomicMax(&d_pool[g * HD + tid], __float_as_int(m));
    }
}

// ---------------------------------------------------------------------------
// redstat: stage-2 reduce (64 blocks) + last-block stats/beff fold.
// ---------------------------------------------------------------------------
__global__ __launch_bounds__(128) void redstat_kernel(const float* __restrict__ Wnext,
                                                      const float* __restrict__ bnext) {
    __shared__ float s_sq[16];
    __shared__ float smean[64];
    __shared__ int   s_last;
    int tid = threadIdx.x;
    int rbase = blockIdx.x * 64;
    if (tid < 64) {
        float s = 0.f;
        for (int r = 0; r < 64; r++) s += d_part[(rbase + r) * 65 + tid];
        d_part2[blockIdx.x * 65 + tid] = s;
    } else if (tid < 80) {
        int j = tid - 64;
        float s = 0.f;
        for (int r = 0; r < 4; r++) s += d_part[(rbase + j * 4 + r) * 65 + 64];
        s_sq[j] = s;
    }
    __syncthreads();
    if (tid == 64) {
        float s = 0.f;
        for (int j = 0; j < 16; j++) s += s_sq[j];
        d_part2[blockIdx.x * 65 + 64] = s;
    }
    __syncthreads();
    __threadfence();
    if (tid == 0) {
        unsigned t = atomicAdd(&d_rc, 1u);
        s_last = (t == 63u);
    }
    __syncthreads();
    if (!s_last) return;

    // ---- stats (one block) ----
    if (tid < 64) {
        float s = 0.f;
        for (int r = 0; r < 64; r++) s += d_part2[r * 65 + tid];
        float mean = s * (1.0f / (float)NPTS);
        smean[tid] = mean;
        d_mean[tid] = mean;
    }
    __syncthreads();
    if (tid == 0) {
        float sq = 0.f;
        for (int r = 0; r < 64; r++) sq += d_part2[r * 65 + 64];
        float ms = 0.f;
        for (int f = 0; f < 64; f++) ms = fmaf(smean[f], smean[f], ms);
        float denom = sq * (1.0f / (float)NPTS) - ms;
        d_scaleInv = 1.0f / sqrtf(PAIRNORM_EPS + denom);
        d_rc = 0;                                    // reset for next invocation
    }
    __syncthreads();
    if (Wnext != nullptr && tid < 64) {
        float inv = d_scaleInv;
        float acc = 0.f;
        for (int k = 0; k < 64; k++) acc = fmaf(smean[k], Wnext[k * HD + tid], acc);
        d_beff[tid] = bnext[tid] - inv * acc;
    }
}

// ---------------------------------------------------------------------------
// head: normalize pooled max, MLP -> out[64,2]. Wl1 staged in smem.
// ---------------------------------------------------------------------------
__global__ __launch_bounds__(128) void head_kernel(const float* __restrict__ Wl1,
                                                   const float* __restrict__ bl1,
                                                   const float* __restrict__ Wl2,
                                                   const float* __restrict__ bl2,
                                                   float* __restrict__ out) {
    __shared__ float hm[BGR * HD];
    __shared__ float t1[BGR * HD];
    __shared__ float sW[HD * HD];
    int tid = threadIdx.x;
    float inv = d_scaleInv;
    const float4* W4 = (const float4*)Wl1;
    float4* sW4 = (float4*)sW;
    for (int i = tid; i < HD * HD / 4; i += 128) sW4[i] = W4[i];
    for (int i = tid; i < BGR * HD; i += 128) {
        int f = i & 63;
        hm[i] = (__int_as_float(d_pool[i]) - d_mean[f]) * inv;
    }
    __syncthreads();

    int g = tid >> 1, half = tid & 1;
    float acc[32];
#pragma unroll
    for (int c = 0; c < 32; c++) acc[c] = bl1[half * 32 + c];
    for (int k = 0; k < HD; k++) {
        float h = hm[g * HD + k];
        const float* wrow = sW + k * HD + half * 32;
#pragma unroll
        for (int c = 0; c < 32; c++) acc[c] = fmaf(h, wrow[c], acc[c]);
    }
#pragma unroll
    for (int c = 0; c < 32; c++) t1[g * HD + half * 32 + c] = fmaxf(acc[c], 0.f);
    __syncthreads();

    int gg = tid >> 1, o = tid & 1;
    float s = bl2[o];
    for (int k = 0; k < HD; k++) s = fmaf(t1[gg * HD + k], Wl2[k * 2 + o], s);
    out[gg * 2 + o] = s;
}

// ---------------------------------------------------------------------------
// launch
// ---------------------------------------------------------------------------
extern "C" void kernel_launch(void* const* d_in, const int* in_sizes, int n_in,
                              void* d_out, int out_size) {
    const float2* pos = (const float2*)d_in[0];
    const float* W1  = (const float*)d_in[2];
    const float* b1  = (const float*)d_in[3];
    const float* W2  = (const float*)d_in[4];
    const float* b2  = (const float*)d_in[5];
    const float* W3  = (const float*)d_in[6];
    const float* b3  = (const float*)d_in[7];
    const float* Wl1 = (const float*)d_in[8];
    const float* bl1 = (const float*)d_in[9];
    const float* Wl2 = (const float*)d_in[10];
    const float* bl2 = (const float*)d_in[11];
    float* out = (float*)d_out;

    reorder_kernel<<<BGR, 256>>>(pos);
    knn_kernel<<<BGR * 2, 1024>>>();

    convA_kernel<<<CONV_BLOCKS, 256>>>(pos, W1, b1, W2);
    redstat_kernel<<<64, 128>>>(W2, b2);

    convB_kernel<<<CONV_BLOCKS, 256>>>(pos, W2, W3);
    redstat_kernel<<<64, 128>>>(W3, b3);

    convC_kernel<<<CONV_BLOCKS, 256>>>(pos, W3);
    redstat_kernel<<<64, 128>>>(nullptr, nullptr);

    head_kernel<<<1, 128>>>(Wl1, bl1, Wl2, bl2, out);
}